// round 13
// baseline (speedup 1.0000x reference)
#include <cuda_runtime.h>
#include <math.h>
#include <stdint.h>

// ---------------------------------------------------------------------------
// Problem constants
// ---------------------------------------------------------------------------
#define MAXB 65536
#define DIM 512
#define MAX_ITER 100

// ---------------------------------------------------------------------------
// Device scratch (static globals: allocation-free rule)
// ---------------------------------------------------------------------------
__device__ float g_feats[MAXB * 8];          //   2 MB
__device__ float g_hs   [MAXB * 512];        // 128 MB (tf32-rounded tanh)
__device__ float g_hc   [MAXB * 512];        // 128 MB (tf32-rounded tanh)
__device__ float g_comb [MAXB * 1024];       // 256 MB (tf32-rounded mirror)
__device__ float g_hn   [MAXB * 512];        // 128 MB (tf32-rounded tanh)
// tf32-rounded weight copies: sW2 | cW2 | nW1 | nW2
#define WR_SW2 0
#define WR_CW2 (512 * 512)
#define WR_NW1 (2 * 512 * 512)
#define WR_NW2 (2 * 512 * 512 + 512 * 1024)
__device__ float g_wr[3 * 512 * 512 + 512 * 1024];   // 5 MB

// ---------------------------------------------------------------------------
// Helpers
// ---------------------------------------------------------------------------
__device__ __forceinline__ float tf32r(float x)
{
    float r;
    asm("cvt.rna.tf32.f32 %0, %1;" : "=f"(r) : "f"(x));
    return r;
}

// m16n8k8 tf32 MMA (sm_80+ family-wide PTX)
__device__ __forceinline__ void mma8(float c[4], const uint32_t a[4],
                                     const uint32_t b[2])
{
    asm volatile(
        "mma.sync.aligned.m16n8k8.row.col.f32.tf32.tf32.f32 "
        "{%0,%1,%2,%3}, {%4,%5,%6,%7}, {%8,%9}, {%0,%1,%2,%3};"
        : "+f"(c[0]), "+f"(c[1]), "+f"(c[2]), "+f"(c[3])
        : "r"(a[0]), "r"(a[1]), "r"(a[2]), "r"(a[3]), "r"(b[0]), "r"(b[1]));
}

// ---------------------------------------------------------------------------
// XLA:CPU (aarch64, contract) complex abs: q=mn/mx; mx*sqrt(fma(q,q,1)); NaN->mn
// ---------------------------------------------------------------------------
__device__ __forceinline__ float xla_cabs(float re, float im)
{
    float a  = fabsf(re);
    float b  = fabsf(im);
    float mx = fmaxf(a, b);
    float mn = fminf(a, b);
    float q  = __fdiv_rn(mn, mx);
    float s  = __fsqrt_rn(__fmaf_rn(q, q, 1.0f));
    float r  = __fmul_rn(mx, s);
    return isnan(r) ? mn : r;
}

// ---------------------------------------------------------------------------
// Kernel 0: tf32-round a float array (weights) into scratch.
// ---------------------------------------------------------------------------
__global__ void round_copy(const float* __restrict__ src,
                           float* __restrict__ dst, int n4)
{
    int i = blockIdx.x * blockDim.x + threadIdx.x;
    if (i >= n4) return;
    float4 v = ((const float4*)src)[i];
    v.x = tf32r(v.x); v.y = tf32r(v.y); v.z = tf32r(v.z); v.w = tf32r(v.w);
    ((float4*)dst)[i] = v;
}

// ---------------------------------------------------------------------------
// Kernel 1: Julia escape-time features (bit-exact contracted-FMA arithmetic;
// warp-coherent early exit once every lane has escaped — results unchanged).
// ---------------------------------------------------------------------------
__global__ void julia_kernel(const float* __restrict__ in,
                             const float* __restrict__ cptr,
                             float* __restrict__ feats, int B)
{
    int i = blockIdx.x * blockDim.x + threadIdx.x;
    if (i >= B) return;
    float x = in[2 * i + 0];
    float y = in[2 * i + 1];
    float cr = cptr[0], ci = cptr[1];

    float zr = x, zi = y;
    int   n   = 0;
    bool  esc = false;

    #pragma unroll 1
    for (int it = 0; it < MAX_ITER; ++it) {
        if (!esc) {
            float bb = __fmul_rn(zi, zi);
            float ab = __fmul_rn(zr, zi);
            float re = __fmaf_rn(zr, zr, -bb);   // fma(a, a, -(b*b))
            float im = __fmaf_rn(zr, zi, ab);    // fma(a, b, a*b)
            float nr = __fadd_rn(re, cr);
            float ni = __fadd_rn(im, ci);
            zr = nr; zi = ni;
            if (xla_cabs(zr, zi) > 2.0f) { n = it; esc = true; }
        }
        if (__all_sync(0xFFFFFFFFu, esc)) break;
    }
    if (!esc) n = MAX_ITER;

    float* f = feats + (size_t)i * 8;
    f[0] = __fdiv_rn((float)n, (float)MAX_ITER);
    f[1] = xla_cabs(zr, zi);
    f[2] = zr;
    f[3] = zi;
    f[4] = x;
    f[5] = y;
    f[6] = cr;
    f[7] = ci;
}

// ---------------------------------------------------------------------------
// Kernel 2: first layers (K=8 effective, full fp32 math). Stores are
// tf32-rounded (hs/hc only feed GEMMs; rounding there == rounding here).
// ---------------------------------------------------------------------------
__global__ __launch_bounds__(256)
void first_layer_kernel(const float* __restrict__ feats,
                        const float* __restrict__ sW1,
                        const float* __restrict__ sb1,
                        const float* __restrict__ cW1,
                        const float* __restrict__ cb1,
                        float* __restrict__ hs,
                        float* __restrict__ hc)
{
    __shared__ float fs[128][8];
    const int tid = threadIdx.x;
    const int m0  = blockIdx.x * 128;
    const int c0  = tid;
    const int c1  = tid + 256;

    float w1a[8], w1b[8], w2a[8], w2b[8];
    *(float4*)&w1a[0] = *(const float4*)(sW1 + (size_t)c0 * DIM);
    *(float4*)&w1a[4] = *(const float4*)(sW1 + (size_t)c0 * DIM + 4);
    *(float4*)&w1b[0] = *(const float4*)(sW1 + (size_t)c1 * DIM);
    *(float4*)&w1b[4] = *(const float4*)(sW1 + (size_t)c1 * DIM + 4);
    *(float4*)&w2a[0] = *(const float4*)(cW1 + (size_t)c0 * DIM);
    *(float4*)&w2a[4] = *(const float4*)(cW1 + (size_t)c0 * DIM + 4);
    *(float4*)&w2b[0] = *(const float4*)(cW1 + (size_t)c1 * DIM);
    *(float4*)&w2b[4] = *(const float4*)(cW1 + (size_t)c1 * DIM + 4);
    float b1a = sb1[c0], b1b = sb1[c1], b2a = cb1[c0], b2b = cb1[c1];

    {
        int r = tid >> 1, h = tid & 1;
        *(float4*)&fs[r][h * 4] = *(const float4*)(feats + (size_t)(m0 + r) * 8 + h * 4);
    }
    __syncthreads();

    #pragma unroll 1
    for (int r = 0; r < 128; ++r) {
        float a1 = b1a, a2 = b1b, a3 = b2a, a4 = b2b;
        #pragma unroll
        for (int k = 0; k < 8; ++k) {
            float fk = fs[r][k];
            a1 = fmaf(fk, w1a[k], a1);
            a2 = fmaf(fk, w1b[k], a2);
            a3 = fmaf(fk, w2a[k], a3);
            a4 = fmaf(fk, w2b[k], a4);
        }
        size_t ro = (size_t)(m0 + r) * DIM;
        hs[ro + c0] = tf32r(tanhf(a1));
        hs[ro + c1] = tf32r(tanhf(a2));
        hc[ro + c0] = tf32r(tanhf(a3));
        hc[ro + c1] = tf32r(tanhf(a4));
    }
}

// ---------------------------------------------------------------------------
// Kernel 3: mma.sync tf32 GEMM, 3-stage cp.async pipeline, one sync/stage.
// All inputs pre-rounded to tf32 in gmem -> mainloop is pure LDGSTS+LDS+MMA.
//   C[m,n] = post( sum_k A[m,k] * W[n,k] + bias[n] )
//   act=0: C = v (fp32), optional C2 = tf32(v)
//   act=1: C = tf32(tanh(v))            (feeds a GEMM only)
// CTA: 128x128 tile, 256 threads = 8 warps (2 x 4). Warp: 64x32 = 4x4
// m16n8 fragments. BK=32, smem stride 36 (conflict-free fragment LDS).
// Buffer-reuse proof: issue(s+2) writes buf (s+2)%3 == (s-1)%3, consumed by
// compute(s-1); the single barrier at top of iter s orders all warps past
// compute(s-1) before any warp issues stage s+2.
// ---------------------------------------------------------------------------
#define SMS 36
#define STG_FLOATS (2 * 128 * SMS)                 // one stage: A tile + B tile
#define NSTAGE 3
#define GEMM_SMEM_BYTES (NSTAGE * STG_FLOATS * 4)  // 110592 B

__global__ __launch_bounds__(256, 2)
void gemm_mma(const float* __restrict__ A, int lda,
              const float* __restrict__ W, int ldw,
              const float* __restrict__ bias,
              float* __restrict__ C, int ldc,
              float* __restrict__ C2, int ldc2,
              int K, int act)
{
    extern __shared__ float sm[];

    const int tid  = threadIdx.x;
    const int wid  = tid >> 5;
    const int lane = tid & 31;
    const int gr   = lane >> 2;        // 0..7
    const int gc   = lane & 3;         // 0..3
    const int m0   = blockIdx.y * 128;
    const int n0   = blockIdx.x * 128;
    const int wm   = (wid >> 2) * 64;  // warp row offset (0 or 64)
    const int wn   = (wid & 3) * 32;   // warp col offset (0,32,64,96)

    uint32_t smb;
    asm("{ .reg .u64 t; cvta.to.shared.u64 t, %1; cvt.u32.u64 %0, t; }"
        : "=r"(smb) : "l"(sm));

    // per-thread copy slots (4 float4 rows for A, 4 for B)
    const int cr_ [4] = { (tid + 0)   >> 3, (tid + 256) >> 3,
                          (tid + 512) >> 3, (tid + 768) >> 3 };
    const int cc4  = tid & 7;

    float acc[4][4][4];
    #pragma unroll
    for (int mt = 0; mt < 4; ++mt)
        #pragma unroll
        for (int nt = 0; nt < 4; ++nt)
            #pragma unroll
            for (int j = 0; j < 4; ++j) acc[mt][nt][j] = 0.0f;

    const int S = K >> 5;

    // --- async copy of stage s into buffer s % NSTAGE ---
    auto issue = [&](int s) {
        const int      buf = s % NSTAGE;
        const int      k0  = s * 32;
        const uint32_t ab  = smb + (uint32_t)(buf * STG_FLOATS) * 4u;
        const uint32_t bb  = ab + 128u * SMS * 4u;
        #pragma unroll
        for (int i = 0; i < 4; ++i) {
            int r = cr_[i];
            uint32_t off = (uint32_t)(r * SMS + cc4 * 4) * 4u;
            const float* sa = A + (size_t)(m0 + r) * lda + k0 + cc4 * 4;
            const float* sb = W + (size_t)(n0 + r) * ldw + k0 + cc4 * 4;
            asm volatile("cp.async.ca.shared.global [%0], [%1], 16;"
                         :: "r"(ab + off), "l"(sa));
            asm volatile("cp.async.ca.shared.global [%0], [%1], 16;"
                         :: "r"(bb + off), "l"(sb));
        }
        asm volatile("cp.async.commit_group;" ::: "memory");
    };

    issue(0);
    issue(1);

    #pragma unroll 1
    for (int s = 0; s < S; ++s) {
        if (s + 1 < S) {
            asm volatile("cp.async.wait_group 1;" ::: "memory");
        } else {
            asm volatile("cp.async.wait_group 0;" ::: "memory");
        }
        __syncthreads();

        const float* As = sm + (s % NSTAGE) * STG_FLOATS;
        const float* Bs = As + 128 * SMS;

        #pragma unroll
        for (int ks = 0; ks < 4; ++ks) {
            const int kb = ks * 8;
            uint32_t a[4][4];
            #pragma unroll
            for (int mt = 0; mt < 4; ++mt) {
                int r0 = wm + mt * 16 + gr;
                a[mt][0] = __float_as_uint(As[r0 * SMS + kb + gc]);
                a[mt][1] = __float_as_uint(As[(r0 + 8) * SMS + kb + gc]);
                a[mt][2] = __float_as_uint(As[r0 * SMS + kb + gc + 4]);
                a[mt][3] = __float_as_uint(As[(r0 + 8) * SMS + kb + gc + 4]);
            }
            #pragma unroll
            for (int nt = 0; nt < 4; ++nt) {
                int nrow = wn + nt * 8 + gr;
                uint32_t b[2];
                b[0] = __float_as_uint(Bs[nrow * SMS + kb + gc]);
                b[1] = __float_as_uint(Bs[nrow * SMS + kb + gc + 4]);
                #pragma unroll
                for (int mt = 0; mt < 4; ++mt)
                    mma8(acc[mt][nt], a[mt], b);
            }
        }

        if (s + 2 < S) issue(s + 2);
    }

    // epilogue
    #pragma unroll
    for (int mt = 0; mt < 4; ++mt) {
        #pragma unroll
        for (int nt = 0; nt < 4; ++nt) {
            int row = m0 + wm + mt * 16 + gr;
            int col = n0 + wn + nt * 8 + gc * 2;
            float2 bb = *(const float2*)(bias + col);
            float v0 = acc[mt][nt][0] + bb.x;
            float v1 = acc[mt][nt][1] + bb.y;
            float v2 = acc[mt][nt][2] + bb.x;
            float v3 = acc[mt][nt][3] + bb.y;
            if (act) {           // tanh output feeds a GEMM -> store rounded
                v0 = tf32r(tanhf(v0)); v1 = tf32r(tanhf(v1));
                v2 = tf32r(tanhf(v2)); v3 = tf32r(tanhf(v3));
            }
            *(float2*)&C[(size_t)row * ldc + col]       = make_float2(v0, v1);
            *(float2*)&C[(size_t)(row + 8) * ldc + col] = make_float2(v2, v3);
            if (C2) {            // mirror feeds a GEMM -> store rounded
                *(float2*)&C2[(size_t)row * ldc2 + col] =
                    make_float2(tf32r(v0), tf32r(v1));
                *(float2*)&C2[(size_t)(row + 8) * ldc2 + col] =
                    make_float2(tf32r(v2), tf32r(v3));
            }
        }
    }
}

// ---------------------------------------------------------------------------
// Kernel 4: row-mean reductions + tail outputs.
// ---------------------------------------------------------------------------
__global__ void reduce_kernel(const float* __restrict__ stab,
                              const float* __restrict__ conn,
                              const float* __restrict__ cptr,
                              float* __restrict__ isin,
                              float* __restrict__ frac,
                              float* __restrict__ jp, int B)
{
    int warp = threadIdx.x >> 5;
    int lane = threadIdx.x & 31;
    int row  = blockIdx.x * 8 + warp;
    if (row < B) {
        const float4* sr = (const float4*)(stab + (size_t)row * DIM);
        const float4* cr = (const float4*)(conn + (size_t)row * DIM);
        float s = 0.0f, c = 0.0f;
        #pragma unroll
        for (int it = 0; it < DIM / 4 / 32; ++it) {
            float4 v = sr[lane + it * 32];
            float4 w = cr[lane + it * 32];
            s += (v.x + v.y) + (v.z + v.w);
            c += (w.x + w.y) + (w.z + w.w);
        }
        #pragma unroll
        for (int o = 16; o > 0; o >>= 1) {
            s += __shfl_xor_sync(0xFFFFFFFFu, s, o);
            c += __shfl_xor_sync(0xFFFFFFFFu, c, o);
        }
        if (lane == 0) {
            float ms = s * (1.0f / (float)DIM);
            float mc = c * (1.0f / (float)DIM);
            isin[row] = (ms > 0.5f) ? 1.0f : 0.0f;
            frac[row] = 1.0f / (1.0f + expf(-mc));
        }
    }
    if (blockIdx.x == 0 && threadIdx.x < 2) jp[threadIdx.x] = cptr[threadIdx.x];
}

// ---------------------------------------------------------------------------
// Launch
// ---------------------------------------------------------------------------
extern "C" void kernel_launch(void* const* d_in, const int* in_sizes, int n_in,
                              void* d_out, int out_size)
{
    const float* input = (const float*)d_in[0];
    const float* c     = (const float*)d_in[1];
    const float* sW1   = (const float*)d_in[2];
    const float* sb1   = (const float*)d_in[3];
    const float* sW2   = (const float*)d_in[4];
    const float* sb2   = (const float*)d_in[5];
    const float* cW1   = (const float*)d_in[6];
    const float* cb1   = (const float*)d_in[7];
    const float* cW2   = (const float*)d_in[8];
    const float* cb2   = (const float*)d_in[9];
    const float* nW1   = (const float*)d_in[10];
    const float* nb1   = (const float*)d_in[11];
    const float* nW2   = (const float*)d_in[12];
    const float* nb2   = (const float*)d_in[13];

    const int B = in_sizes[0] / 2;

    float* out      = (float*)d_out;
    float* out_stab = out;
    float* out_cyc  = out + (size_t)B * DIM;
    float* out_conn = out + (size_t)2 * B * DIM;
    float* out_isin = out + (size_t)3 * B * DIM;
    float* out_frac = out_isin + B;
    float* out_jp   = out_frac + B;

    float *feats, *hs, *hc, *comb, *hn, *wr;
    cudaGetSymbolAddress((void**)&feats, g_feats);
    cudaGetSymbolAddress((void**)&hs,    g_hs);
    cudaGetSymbolAddress((void**)&hc,    g_hc);
    cudaGetSymbolAddress((void**)&comb,  g_comb);
    cudaGetSymbolAddress((void**)&hn,    g_hn);
    cudaGetSymbolAddress((void**)&wr,    g_wr);

    cudaFuncSetAttribute(gemm_mma, cudaFuncAttributeMaxDynamicSharedMemorySize,
                         GEMM_SMEM_BYTES);

    // 0) tf32-round the GEMM weights into scratch
    round_copy<<<(512 * 512 / 4 + 255) / 256, 256>>>(sW2, wr + WR_SW2, 512 * 512 / 4);
    round_copy<<<(512 * 512 / 4 + 255) / 256, 256>>>(cW2, wr + WR_CW2, 512 * 512 / 4);
    round_copy<<<(512 * 1024 / 4 + 255) / 256, 256>>>(nW1, wr + WR_NW1, 512 * 1024 / 4);
    round_copy<<<(512 * 512 / 4 + 255) / 256, 256>>>(nW2, wr + WR_NW2, 512 * 512 / 4);

    // 1) Julia features
    julia_kernel<<<(B + 255) / 256, 256>>>(input, c, feats, B);

    // 2) First layers (K=8) for stability + cycle MLPs
    first_layer_kernel<<<B / 128, 256>>>(feats, sW1, sb1, cW1, cb1, hs, hc);

    dim3 ggrid(DIM / 128, B / 128);

    // 3) stability = hs @ sW2.T + sb2   (rounded mirror into combined[:, :512])
    gemm_mma<<<ggrid, 256, GEMM_SMEM_BYTES>>>(hs, DIM, wr + WR_SW2, DIM, sb2,
                                              out_stab, DIM, comb, 2 * DIM, DIM, 0);

    // 4) cycle = hc @ cW2.T + cb2       (rounded mirror into combined[:, 512:])
    gemm_mma<<<ggrid, 256, GEMM_SMEM_BYTES>>>(hc, DIM, wr + WR_CW2, DIM, cb2,
                                              out_cyc, DIM, comb + DIM, 2 * DIM, DIM, 0);

    // 5) hn = tf32(tanh(combined @ nW1.T + nb1))   (K = 1024)
    gemm_mma<<<ggrid, 256, GEMM_SMEM_BYTES>>>(comb, 2 * DIM, wr + WR_NW1, 2 * DIM, nb1,
                                              hn, DIM, nullptr, 0, 2 * DIM, 1);

    // 6) connection = hn @ nW2.T + nb2
    gemm_mma<<<ggrid, 256, GEMM_SMEM_BYTES>>>(hn, DIM, wr + WR_NW2, DIM, nb2,
                                              out_conn, DIM, nullptr, 0, DIM, 0);

    // 7) reductions + julia_parameter passthrough
    reduce_kernel<<<(B + 7) / 8, 256>>>(out_stab, out_conn, c,
                                        out_isin, out_frac, out_jp, B);
}

// round 14
// speedup vs baseline: 1.1482x; 1.1482x over previous
#include <cuda_runtime.h>
#include <math.h>
#include <stdint.h>

// ---------------------------------------------------------------------------
// Problem constants
// ---------------------------------------------------------------------------
#define MAXB 65536
#define DIM 512
#define MAX_ITER 100

// ---------------------------------------------------------------------------
// Device scratch (static globals: allocation-free rule)
// ---------------------------------------------------------------------------
__device__ float g_feats[MAXB * 8];          //   2 MB
__device__ float g_hs   [MAXB * 512];        // 128 MB (tf32-rounded tanh)
__device__ float g_hc   [MAXB * 512];        // 128 MB (tf32-rounded tanh)
__device__ float g_comb [MAXB * 1024];       // 256 MB (tf32-rounded mirror)
__device__ float g_hn   [MAXB * 512];        // 128 MB (tf32-rounded tanh)
// tf32-rounded weight copies: sW2 | cW2 | nW1 | nW2
#define WR_SW2 0
#define WR_CW2 (512 * 512)
#define WR_NW1 (2 * 512 * 512)
#define WR_NW2 (2 * 512 * 512 + 512 * 1024)
__device__ float g_wr[3 * 512 * 512 + 512 * 1024];   // 5 MB

// ---------------------------------------------------------------------------
// Helpers
// ---------------------------------------------------------------------------
__device__ __forceinline__ float tf32r(float x)
{
    float r;
    asm("cvt.rna.tf32.f32 %0, %1;" : "=f"(r) : "f"(x));
    return r;
}

// m16n8k8 tf32 MMA (sm_80+ family-wide PTX)
__device__ __forceinline__ void mma8(float c[4], const uint32_t a[4],
                                     const uint32_t b[2])
{
    asm volatile(
        "mma.sync.aligned.m16n8k8.row.col.f32.tf32.tf32.f32 "
        "{%0,%1,%2,%3}, {%4,%5,%6,%7}, {%8,%9}, {%0,%1,%2,%3};"
        : "+f"(c[0]), "+f"(c[1]), "+f"(c[2]), "+f"(c[3])
        : "r"(a[0]), "r"(a[1]), "r"(a[2]), "r"(a[3]), "r"(b[0]), "r"(b[1]));
}

// ---------------------------------------------------------------------------
// XLA:CPU (aarch64, contract) complex abs: q=mn/mx; mx*sqrt(fma(q,q,1)); NaN->mn
// ---------------------------------------------------------------------------
__device__ __forceinline__ float xla_cabs(float re, float im)
{
    float a  = fabsf(re);
    float b  = fabsf(im);
    float mx = fmaxf(a, b);
    float mn = fminf(a, b);
    float q  = __fdiv_rn(mn, mx);
    float s  = __fsqrt_rn(__fmaf_rn(q, q, 1.0f));
    float r  = __fmul_rn(mx, s);
    return isnan(r) ? mn : r;
}

// ---------------------------------------------------------------------------
// Kernel 0: tf32-round a float array (weights) into scratch.
// ---------------------------------------------------------------------------
__global__ void round_copy(const float* __restrict__ src,
                           float* __restrict__ dst, int n4)
{
    int i = blockIdx.x * blockDim.x + threadIdx.x;
    if (i >= n4) return;
    float4 v = ((const float4*)src)[i];
    v.x = tf32r(v.x); v.y = tf32r(v.y); v.z = tf32r(v.z); v.w = tf32r(v.w);
    ((float4*)dst)[i] = v;
}

// ---------------------------------------------------------------------------
// Kernel 1: Julia escape-time features (bit-exact contracted-FMA arithmetic;
// warp-coherent early exit once every lane has escaped — results unchanged).
// ---------------------------------------------------------------------------
__global__ void julia_kernel(const float* __restrict__ in,
                             const float* __restrict__ cptr,
                             float* __restrict__ feats, int B)
{
    int i = blockIdx.x * blockDim.x + threadIdx.x;
    if (i >= B) return;
    float x = in[2 * i + 0];
    float y = in[2 * i + 1];
    float cr = cptr[0], ci = cptr[1];

    float zr = x, zi = y;
    int   n   = 0;
    bool  esc = false;

    #pragma unroll 1
    for (int it = 0; it < MAX_ITER; ++it) {
        if (!esc) {
            float bb = __fmul_rn(zi, zi);
            float ab = __fmul_rn(zr, zi);
            float re = __fmaf_rn(zr, zr, -bb);   // fma(a, a, -(b*b))
            float im = __fmaf_rn(zr, zi, ab);    // fma(a, b, a*b)
            float nr = __fadd_rn(re, cr);
            float ni = __fadd_rn(im, ci);
            zr = nr; zi = ni;
            if (xla_cabs(zr, zi) > 2.0f) { n = it; esc = true; }
        }
        if (__all_sync(0xFFFFFFFFu, esc)) break;
    }
    if (!esc) n = MAX_ITER;

    float* f = feats + (size_t)i * 8;
    f[0] = __fdiv_rn((float)n, (float)MAX_ITER);
    f[1] = xla_cabs(zr, zi);
    f[2] = zr;
    f[3] = zi;
    f[4] = x;
    f[5] = y;
    f[6] = cr;
    f[7] = ci;
}

// ---------------------------------------------------------------------------
// Kernel 2: first layers (K=8 effective, full fp32 math). Stores are
// tf32-rounded (hs/hc only feed GEMMs; rounding there == rounding here).
// ---------------------------------------------------------------------------
__global__ __launch_bounds__(256)
void first_layer_kernel(const float* __restrict__ feats,
                        const float* __restrict__ sW1,
                        const float* __restrict__ sb1,
                        const float* __restrict__ cW1,
                        const float* __restrict__ cb1,
                        float* __restrict__ hs,
                        float* __restrict__ hc)
{
    __shared__ float fs[128][8];
    const int tid = threadIdx.x;
    const int m0  = blockIdx.x * 128;
    const int c0  = tid;
    const int c1  = tid + 256;

    float w1a[8], w1b[8], w2a[8], w2b[8];
    *(float4*)&w1a[0] = *(const float4*)(sW1 + (size_t)c0 * DIM);
    *(float4*)&w1a[4] = *(const float4*)(sW1 + (size_t)c0 * DIM + 4);
    *(float4*)&w1b[0] = *(const float4*)(sW1 + (size_t)c1 * DIM);
    *(float4*)&w1b[4] = *(const float4*)(sW1 + (size_t)c1 * DIM + 4);
    *(float4*)&w2a[0] = *(const float4*)(cW1 + (size_t)c0 * DIM);
    *(float4*)&w2a[4] = *(const float4*)(cW1 + (size_t)c0 * DIM + 4);
    *(float4*)&w2b[0] = *(const float4*)(cW1 + (size_t)c1 * DIM);
    *(float4*)&w2b[4] = *(const float4*)(cW1 + (size_t)c1 * DIM + 4);
    float b1a = sb1[c0], b1b = sb1[c1], b2a = cb1[c0], b2b = cb1[c1];

    {
        int r = tid >> 1, h = tid & 1;
        *(float4*)&fs[r][h * 4] = *(const float4*)(feats + (size_t)(m0 + r) * 8 + h * 4);
    }
    __syncthreads();

    #pragma unroll 1
    for (int r = 0; r < 128; ++r) {
        float a1 = b1a, a2 = b1b, a3 = b2a, a4 = b2b;
        #pragma unroll
        for (int k = 0; k < 8; ++k) {
            float fk = fs[r][k];
            a1 = fmaf(fk, w1a[k], a1);
            a2 = fmaf(fk, w1b[k], a2);
            a3 = fmaf(fk, w2a[k], a3);
            a4 = fmaf(fk, w2b[k], a4);
        }
        size_t ro = (size_t)(m0 + r) * DIM;
        hs[ro + c0] = tf32r(tanhf(a1));
        hs[ro + c1] = tf32r(tanhf(a2));
        hc[ro + c0] = tf32r(tanhf(a3));
        hc[ro + c1] = tf32r(tanhf(a4));
    }
}

// ---------------------------------------------------------------------------
// Kernel 3: mma.sync tf32 GEMM, cp.async double-buffered (R11 pipeline),
// 64x64 warp tiles: 128 threads = 4 warps (2 x 2), CTA tile 128x128.
// A-fragments amortize over 8 N-tiles -> LDS/MMA ratio 1.0 (was 1.5).
// All inputs pre-rounded to tf32 in gmem -> mainloop pure LDGSTS+LDS+MMA.
//   C[m,n] = post( sum_k A[m,k] * W[n,k] + bias[n] )
//   act=0: C = v (fp32), optional C2 = tf32(v)
//   act=1: C = tf32(tanh(v))            (feeds a GEMM only)
// BK=32, smem stride 36 (conflict-free fragment LDS), 72KB -> 2 CTAs/SM.
// ---------------------------------------------------------------------------
#define SMS 36
#define STG_FLOATS (2 * 128 * SMS)                 // one stage: A tile + B tile
#define GEMM_SMEM_BYTES (2 * STG_FLOATS * 4)       // two stages: 73728 B

__global__ __launch_bounds__(128, 2)
void gemm_mma(const float* __restrict__ A, int lda,
              const float* __restrict__ W, int ldw,
              const float* __restrict__ bias,
              float* __restrict__ C, int ldc,
              float* __restrict__ C2, int ldc2,
              int K, int act)
{
    extern __shared__ float sm[];

    const int tid  = threadIdx.x;
    const int wid  = tid >> 5;
    const int lane = tid & 31;
    const int gr   = lane >> 2;        // 0..7
    const int gc   = lane & 3;         // 0..3
    const int m0   = blockIdx.y * 128;
    const int n0   = blockIdx.x * 128;
    const int wm   = (wid >> 1) * 64;  // warp row offset (0 or 64)
    const int wn   = (wid & 1) * 64;   // warp col offset (0 or 64)

    uint32_t smb;
    asm("{ .reg .u64 t; cvta.to.shared.u64 t, %1; cvt.u32.u64 %0, t; }"
        : "=r"(smb) : "l"(sm));

    // per-thread copy slots: 8 float4 rows for A, 8 for B (128 threads)
    const int cc4 = tid & 7;

    float acc[4][8][4];
    #pragma unroll
    for (int mt = 0; mt < 4; ++mt)
        #pragma unroll
        for (int nt = 0; nt < 8; ++nt)
            #pragma unroll
            for (int j = 0; j < 4; ++j) acc[mt][nt][j] = 0.0f;

    const int S = K >> 5;

    // --- async copy of stage s into buffer (s&1) ---
    auto issue = [&](int s) {
        const int      buf = s & 1;
        const int      k0  = s * 32;
        const uint32_t ab  = smb + (uint32_t)(buf * STG_FLOATS) * 4u;
        const uint32_t bb  = ab + 128u * SMS * 4u;
        #pragma unroll
        for (int i = 0; i < 8; ++i) {
            int r = (tid + i * 128) >> 3;
            uint32_t off = (uint32_t)(r * SMS + cc4 * 4) * 4u;
            const float* sa = A + (size_t)(m0 + r) * lda + k0 + cc4 * 4;
            const float* sb = W + (size_t)(n0 + r) * ldw + k0 + cc4 * 4;
            asm volatile("cp.async.ca.shared.global [%0], [%1], 16;"
                         :: "r"(ab + off), "l"(sa));
            asm volatile("cp.async.ca.shared.global [%0], [%1], 16;"
                         :: "r"(bb + off), "l"(sb));
        }
        asm volatile("cp.async.commit_group;" ::: "memory");
    };

    issue(0);

    #pragma unroll 1
    for (int s = 0; s < S; ++s) {
        if (s) __syncthreads();              // compute(s-1) done before overwrite
        if (s + 1 < S) {
            issue(s + 1);
            asm volatile("cp.async.wait_group 1;" ::: "memory");
        } else {
            asm volatile("cp.async.wait_group 0;" ::: "memory");
        }
        __syncthreads();

        const float* As = sm + (s & 1) * STG_FLOATS;
        const float* Bs = As + 128 * SMS;

        #pragma unroll
        for (int ks = 0; ks < 4; ++ks) {
            const int kb = ks * 8;
            uint32_t a[4][4];
            #pragma unroll
            for (int mt = 0; mt < 4; ++mt) {
                int r0 = wm + mt * 16 + gr;
                a[mt][0] = __float_as_uint(As[r0 * SMS + kb + gc]);
                a[mt][1] = __float_as_uint(As[(r0 + 8) * SMS + kb + gc]);
                a[mt][2] = __float_as_uint(As[r0 * SMS + kb + gc + 4]);
                a[mt][3] = __float_as_uint(As[(r0 + 8) * SMS + kb + gc + 4]);
            }
            #pragma unroll
            for (int nt = 0; nt < 8; ++nt) {
                int nrow = wn + nt * 8 + gr;
                uint32_t b[2];
                b[0] = __float_as_uint(Bs[nrow * SMS + kb + gc]);
                b[1] = __float_as_uint(Bs[nrow * SMS + kb + gc + 4]);
                #pragma unroll
                for (int mt = 0; mt < 4; ++mt)
                    mma8(acc[mt][nt], a[mt], b);
            }
        }
    }

    // epilogue
    #pragma unroll
    for (int mt = 0; mt < 4; ++mt) {
        #pragma unroll
        for (int nt = 0; nt < 8; ++nt) {
            int row = m0 + wm + mt * 16 + gr;
            int col = n0 + wn + nt * 8 + gc * 2;
            float2 bb = *(const float2*)(bias + col);
            float v0 = acc[mt][nt][0] + bb.x;
            float v1 = acc[mt][nt][1] + bb.y;
            float v2 = acc[mt][nt][2] + bb.x;
            float v3 = acc[mt][nt][3] + bb.y;
            if (act) {           // tanh output feeds a GEMM -> store rounded
                v0 = tf32r(tanhf(v0)); v1 = tf32r(tanhf(v1));
                v2 = tf32r(tanhf(v2)); v3 = tf32r(tanhf(v3));
            }
            *(float2*)&C[(size_t)row * ldc + col]       = make_float2(v0, v1);
            *(float2*)&C[(size_t)(row + 8) * ldc + col] = make_float2(v2, v3);
            if (C2) {            // mirror feeds a GEMM -> store rounded
                *(float2*)&C2[(size_t)row * ldc2 + col] =
                    make_float2(tf32r(v0), tf32r(v1));
                *(float2*)&C2[(size_t)(row + 8) * ldc2 + col] =
                    make_float2(tf32r(v2), tf32r(v3));
            }
        }
    }
}

// ---------------------------------------------------------------------------
// Kernel 4: row-mean reductions + tail outputs.
// ---------------------------------------------------------------------------
__global__ void reduce_kernel(const float* __restrict__ stab,
                              const float* __restrict__ conn,
                              const float* __restrict__ cptr,
                              float* __restrict__ isin,
                              float* __restrict__ frac,
                              float* __restrict__ jp, int B)
{
    int warp = threadIdx.x >> 5;
    int lane = threadIdx.x & 31;
    int row  = blockIdx.x * 8 + warp;
    if (row < B) {
        const float4* sr = (const float4*)(stab + (size_t)row * DIM);
        const float4* cr = (const float4*)(conn + (size_t)row * DIM);
        float s = 0.0f, c = 0.0f;
        #pragma unroll
        for (int it = 0; it < DIM / 4 / 32; ++it) {
            float4 v = sr[lane + it * 32];
            float4 w = cr[lane + it * 32];
            s += (v.x + v.y) + (v.z + v.w);
            c += (w.x + w.y) + (w.z + w.w);
        }
        #pragma unroll
        for (int o = 16; o > 0; o >>= 1) {
            s += __shfl_xor_sync(0xFFFFFFFFu, s, o);
            c += __shfl_xor_sync(0xFFFFFFFFu, c, o);
        }
        if (lane == 0) {
            float ms = s * (1.0f / (float)DIM);
            float mc = c * (1.0f / (float)DIM);
            isin[row] = (ms > 0.5f) ? 1.0f : 0.0f;
            frac[row] = 1.0f / (1.0f + expf(-mc));
        }
    }
    if (blockIdx.x == 0 && threadIdx.x < 2) jp[threadIdx.x] = cptr[threadIdx.x];
}

// ---------------------------------------------------------------------------
// Launch
// ---------------------------------------------------------------------------
extern "C" void kernel_launch(void* const* d_in, const int* in_sizes, int n_in,
                              void* d_out, int out_size)
{
    const float* input = (const float*)d_in[0];
    const float* c     = (const float*)d_in[1];
    const float* sW1   = (const float*)d_in[2];
    const float* sb1   = (const float*)d_in[3];
    const float* sW2   = (const float*)d_in[4];
    const float* sb2   = (const float*)d_in[5];
    const float* cW1   = (const float*)d_in[6];
    const float* cb1   = (const float*)d_in[7];
    const float* cW2   = (const float*)d_in[8];
    const float* cb2   = (const float*)d_in[9];
    const float* nW1   = (const float*)d_in[10];
    const float* nb1   = (const float*)d_in[11];
    const float* nW2   = (const float*)d_in[12];
    const float* nb2   = (const float*)d_in[13];

    const int B = in_sizes[0] / 2;

    float* out      = (float*)d_out;
    float* out_stab = out;
    float* out_cyc  = out + (size_t)B * DIM;
    float* out_conn = out + (size_t)2 * B * DIM;
    float* out_isin = out + (size_t)3 * B * DIM;
    float* out_frac = out_isin + B;
    float* out_jp   = out_frac + B;

    float *feats, *hs, *hc, *comb, *hn, *wr;
    cudaGetSymbolAddress((void**)&feats, g_feats);
    cudaGetSymbolAddress((void**)&hs,    g_hs);
    cudaGetSymbolAddress((void**)&hc,    g_hc);
    cudaGetSymbolAddress((void**)&comb,  g_comb);
    cudaGetSymbolAddress((void**)&hn,    g_hn);
    cudaGetSymbolAddress((void**)&wr,    g_wr);

    cudaFuncSetAttribute(gemm_mma, cudaFuncAttributeMaxDynamicSharedMemorySize,
                         GEMM_SMEM_BYTES);

    // 0) tf32-round the GEMM weights into scratch
    round_copy<<<(512 * 512 / 4 + 255) / 256, 256>>>(sW2, wr + WR_SW2, 512 * 512 / 4);
    round_copy<<<(512 * 512 / 4 + 255) / 256, 256>>>(cW2, wr + WR_CW2, 512 * 512 / 4);
    round_copy<<<(512 * 1024 / 4 + 255) / 256, 256>>>(nW1, wr + WR_NW1, 512 * 1024 / 4);
    round_copy<<<(512 * 512 / 4 + 255) / 256, 256>>>(nW2, wr + WR_NW2, 512 * 512 / 4);

    // 1) Julia features
    julia_kernel<<<(B + 255) / 256, 256>>>(input, c, feats, B);

    // 2) First layers (K=8) for stability + cycle MLPs
    first_layer_kernel<<<B / 128, 256>>>(feats, sW1, sb1, cW1, cb1, hs, hc);

    dim3 ggrid(DIM / 128, B / 128);

    // 3) stability = hs @ sW2.T + sb2   (rounded mirror into combined[:, :512])
    gemm_mma<<<ggrid, 128, GEMM_SMEM_BYTES>>>(hs, DIM, wr + WR_SW2, DIM, sb2,
                                              out_stab, DIM, comb, 2 * DIM, DIM, 0);

    // 4) cycle = hc @ cW2.T + cb2       (rounded mirror into combined[:, 512:])
    gemm_mma<<<ggrid, 128, GEMM_SMEM_BYTES>>>(hc, DIM, wr + WR_CW2, DIM, cb2,
                                              out_cyc, DIM, comb + DIM, 2 * DIM, DIM, 0);

    // 5) hn = tf32(tanh(combined @ nW1.T + nb1))   (K = 1024)
    gemm_mma<<<ggrid, 128, GEMM_SMEM_BYTES>>>(comb, 2 * DIM, wr + WR_NW1, 2 * DIM, nb1,
                                              hn, DIM, nullptr, 0, 2 * DIM, 1);

    // 6) connection = hn @ nW2.T + nb2
    gemm_mma<<<ggrid, 128, GEMM_SMEM_BYTES>>>(hn, DIM, wr + WR_NW2, DIM, nb2,
                                              out_conn, DIM, nullptr, 0, DIM, 0);

    // 7) reductions + julia_parameter passthrough
    reduce_kernel<<<(B + 7) / 8, 256>>>(out_stab, out_conn, c,
                                        out_isin, out_frac, out_jp, B);
}